// round 12
// baseline (speedup 1.0000x reference)
#include <cuda_runtime.h>
#include <cstdint>

// Depthwise Conv1d, K=3, pad=1, stride=1.
// inputs: [B=32, C=128, L=8192] f32, weight: [128,3] f32, bias: [128] f32
// out[b,c,l] = w0*x[l-1] + w1*x[l] + w2*x[l+1] + bias  (x zero-padded)
//
// Coalesced layout (proven R11): warp owns 512 contiguous elems as 4 chunks
// of 128; in chunk j lane i holds float4 at j*128+4i -> every warp-wide
// LDG.128/STG.128 spans exactly 512 contiguous bytes (min L1 wavefronts).
// Halos via ROTATE-shuffle: one shfl per chunk per side handles both the
// intra-chunk shift and the cross-chunk seam (lane 31/0 contribute the
// neighboring chunk's edge value). Warp-tile edges: 2 scalar loads.

#define C_CH       128
#define L_LEN      8192
#define WARP_TILE  512                        // elems per warp (4 chunks x 128)
#define TILES_PER_ROW (L_LEN / WARP_TILE)     // 16
#define TOTAL_ROWS (32 * C_CH)                // 4096
#define FULL 0xffffffffu

__global__ __launch_bounds__(256, 7)
void dwconv1d_kernel(const float* __restrict__ x,
                     const float* __restrict__ w,
                     const float* __restrict__ b,
                     float* __restrict__ y) {
    const int gtid   = blockIdx.x * blockDim.x + threadIdx.x;
    const int lane   = threadIdx.x & 31;
    const int warpId = gtid >> 5;
    const int row    = warpId >> 4;            // /16 -> (b*C + c), warp-uniform
    const int tile   = warpId & 15;            // warp tile within row
    const int base   = tile * WARP_TILE;       // warp-uniform
    const int c      = row & (C_CH - 1);

    const float* __restrict__ xr = x + (size_t)row * L_LEN + base;
    float*       __restrict__ yr = y + (size_t)row * L_LEN + base;
    const int lo = lane * 4;

    // Front-batched coalesced loads: 4 x LDG.128, each warp-wide = 512 B.
    float4 v[4];
#pragma unroll
    for (int j = 0; j < 4; j++)
        v[j] = *reinterpret_cast<const float4*>(xr + j * 128 + lo);

    // Warp-tile edge halos (1 active lane each; L2 hits).
    float xl_edge = 0.0f, xh_edge = 0.0f;
    if (lane == 0 && base != 0)
        xl_edge = xr[-1];
    if (lane == 31 && base != L_LEN - WARP_TILE)
        xh_edge = xr[WARP_TILE];

    // Rotate-shuffle halos: one shfl per chunk per side.
    // Left halo of chunk j, lane i = elem j*128+4i-1:
    //   lanes 1..31 <- lane i-1's v[j].w ; lane 0 <- lane 31's v[j-1].w.
    // So lane 31 contributes v[j-1].w, everyone else v[j].w, rotate by -1.
    float xl[4], xh[4];
#pragma unroll
    for (int j = 0; j < 4; j++) {
        const float tl = (lane == 31 && j > 0) ? v[j - 1].w : v[j].w;
        const float th = (lane == 0  && j < 3) ? v[j + 1].x : v[j].x;
        xl[j] = __shfl_sync(FULL, tl, (lane + 31) & 31);
        xh[j] = __shfl_sync(FULL, th, (lane + 1) & 31);
    }
    if (lane == 0)  xl[0] = xl_edge;
    if (lane == 31) xh[3] = xh_edge;

    // Warp-uniform coefficients.
    const float w0 = w[3 * c + 0];
    const float w1 = w[3 * c + 1];
    const float w2 = w[3 * c + 2];
    const float bb = b[c];

    // Compute, overwriting input registers with outputs.
#pragma unroll
    for (int j = 0; j < 4; j++) {
        const float e0 = v[j].x, e1 = v[j].y, e2 = v[j].z, e3 = v[j].w;
        float4 o;
        o.x = fmaf(w0, xl[j], fmaf(w1, e0, fmaf(w2, e1, bb)));
        o.y = fmaf(w0, e0,    fmaf(w1, e1, fmaf(w2, e2, bb)));
        o.z = fmaf(w0, e1,    fmaf(w1, e2, fmaf(w2, e3, bb)));
        o.w = fmaf(w0, e2,    fmaf(w1, e3, fmaf(w2, xh[j], bb)));
        v[j] = o;
    }

    // Coalesced stores: 4 x STG.128, each warp-wide = 512 B.
#pragma unroll
    for (int j = 0; j < 4; j++)
        *reinterpret_cast<float4*>(yr + j * 128 + lo) = v[j];
}

extern "C" void kernel_launch(void* const* d_in, const int* in_sizes, int n_in,
                              void* d_out, int out_size) {
    const float* x = (const float*)d_in[0];   // inputs [32,128,8192]
    const float* w = (const float*)d_in[1];   // weight [128,3]
    const float* b = (const float*)d_in[2];   // bias   [128]
    float* y = (float*)d_out;

    const int total_warps   = TOTAL_ROWS * TILES_PER_ROW;    // 65536
    const int total_threads = total_warps * 32;              // 2,097,152
    dwconv1d_kernel<<<total_threads / 256, 256>>>(x, w, b, y);
}